// round 10
// baseline (speedup 1.0000x reference)
#include <cuda_runtime.h>
#include <cuda_fp16.h>
#include <cstdint>

#define TOKS 4096
#define HID  2048
#define INTD 1024
#define NE   8

typedef __half fp16;

// ---------------- persistent device scratch ----------------------------------
__device__ int   g_counts[NE];
__device__ int   g_tok [NE * TOKS];
__device__ float g_wt  [NE * TOKS];
__device__ fp16  g_xsh [TOKS * HID];
__device__ fp16  g_wgh [NE * INTD * HID];
__device__ fp16  g_wuh [NE * INTD * HID];
__device__ fp16  g_wdh [NE * HID * INTD];
__device__ fp16  g_acth[(size_t)NE * TOKS * INTD];

// ---------------- asm helpers -------------------------------------------------
__device__ __forceinline__ uint32_t smem_u32(const void* p) {
    return (uint32_t)__cvta_generic_to_shared(p);
}

#define CPA(s, g)  asm volatile("cp.async.cg.shared.global [%0], [%1], 16;" :: "r"(s), "l"(g))
#define CPC()      asm volatile("cp.async.commit_group;" ::: "memory")
#define CPW(n)     asm volatile("cp.async.wait_group %0;" :: "n"(n) : "memory")

#define LDM4(r, addr)                                                           \
    asm volatile("ldmatrix.sync.aligned.m8n8.x4.shared.b16 {%0,%1,%2,%3}, [%4];" \
        : "=r"((r)[0]), "=r"((r)[1]), "=r"((r)[2]), "=r"((r)[3]) : "r"(addr))

#define MMA(c, a, b0, b1)                                                       \
    asm volatile("mma.sync.aligned.m16n8k16.row.col.f32.f16.f16.f32 "            \
        "{%0,%1,%2,%3},{%4,%5,%6,%7},{%8,%9},{%0,%1,%2,%3};"                     \
        : "+f"((c)[0]), "+f"((c)[1]), "+f"((c)[2]), "+f"((c)[3])                 \
        : "r"((a)[0]), "r"((a)[1]), "r"((a)[2]), "r"((a)[3]), "r"(b0), "r"(b1))

// ================= kernel: zero out + counts ==================================
__global__ void __launch_bounds__(256) k_zero(float4* __restrict__ out, int n4) {
    int i = blockIdx.x * 256 + threadIdx.x;
    if (i < n4) out[i] = make_float4(0.f, 0.f, 0.f, 0.f);
    if (blockIdx.x == 0 && threadIdx.x < NE) g_counts[threadIdx.x] = 0;
}

// ================= kernel: fused fp32 -> fp16 conversion ======================
#define R_X  (TOKS * HID / 4)
#define R_W  (NE * INTD * HID / 4)
__global__ void __launch_bounds__(256)
k_cvt_all(const float4* __restrict__ x,  const float4* __restrict__ wg,
          const float4* __restrict__ wu, const float4* __restrict__ wd) {
    int base = (blockIdx.x * 256 + threadIdx.x) * 2;
    const float4* src;
    __half2* dst;
    int local;
    if (base < R_X)                { src = x;  dst = (__half2*)g_xsh; local = base; }
    else if (base < R_X + R_W)     { src = wg; dst = (__half2*)g_wgh; local = base - R_X; }
    else if (base < R_X + 2 * R_W) { src = wu; dst = (__half2*)g_wuh; local = base - R_X - R_W; }
    else                           { src = wd; dst = (__half2*)g_wdh; local = base - R_X - 2 * R_W; }
#pragma unroll
    for (int j = 0; j < 2; j++) {
        float4 v = src[local + j];
        __half2 hp0, hp1;
        hp0.x = __float2half_rn(v.x); hp0.y = __float2half_rn(v.y);
        hp1.x = __float2half_rn(v.z); hp1.y = __float2half_rn(v.w);
        dst[(local + j) * 2]     = hp0;
        dst[(local + j) * 2 + 1] = hp1;
    }
}

// ================= kernel: router (warp per token) ============================
__global__ void __launch_bounds__(256) k_router(const float* __restrict__ x,
                                                const float* __restrict__ gw) {
    int t    = blockIdx.x * 8 + (threadIdx.x >> 5);
    int lane = threadIdx.x & 31;
    if (t >= TOKS) return;
    const float* h = x + (size_t)t * HID;

    float acc[NE];
#pragma unroll
    for (int e = 0; e < NE; e++) acc[e] = 0.0f;
    for (int i = lane; i < HID; i += 32) {
        float hv = h[i];
#pragma unroll
        for (int e = 0; e < NE; e++) acc[e] += hv * gw[e * HID + i];
    }
#pragma unroll
    for (int e = 0; e < NE; e++)
#pragma unroll
        for (int o = 16; o; o >>= 1) acc[e] += __shfl_xor_sync(0xFFFFFFFFu, acc[e], o);

    if (lane == 0) {
        float mx = acc[0];
#pragma unroll
        for (int e = 1; e < NE; e++) mx = fmaxf(mx, acc[e]);
        float p[NE], s = 0.0f;
#pragma unroll
        for (int e = 0; e < NE; e++) { p[e] = expf(acc[e] - mx); s += p[e]; }
#pragma unroll
        for (int e = 0; e < NE; e++) p[e] /= s;

        int i1 = 0;
#pragma unroll
        for (int e = 1; e < NE; e++) if (p[e] > p[i1]) i1 = e;
        int i2 = (i1 == 0) ? 1 : 0;
#pragma unroll
        for (int e = 0; e < NE; e++) if (e != i1 && p[e] > p[i2]) i2 = e;

        float denom = p[i1] + p[i2];
        int pos = atomicAdd(&g_counts[i1], 1);
        g_tok[i1 * TOKS + pos] = t;
        g_wt [i1 * TOKS + pos] = p[i1] / denom;
        pos = atomicAdd(&g_counts[i2], 1);
        g_tok[i2 * TOKS + pos] = t;
        g_wt [i2 * TOKS + pos] = p[i2] / denom;
    }
}

// ================= GEMM common: 128-thread CTAs, BK=64, 3-stage 32KB ==========
// stage: [A 16K: 128 rows x 128B][B 16K: 128 rows x 128B], swizzle ch^=(row&7)
#define STAGE_BYTES 32768
#define NSTAGE 3
#define SMEM_MAIN (NSTAGE * STAGE_BYTES)

// ================= kernel: gate+up GEMM + SiLU ================================
// CTA tile: M=128 tokens x N=64 inter (B: gate rows 0-63, up rows 64-127)
// 4 warps: wm=(wid&1)*64, wn=(wid>>1)*32; warp tile 64 x (32g+32u)
__global__ void __launch_bounds__(128, 2)
k2_gateup() {
    extern __shared__ char smem[];
    const int e     = blockIdx.x >> 5;
    const int mtile = blockIdx.x & 31;
    const int ntile = blockIdx.y;
    const int cnt   = g_counts[e];
    if (mtile * 128 >= cnt) return;

    const int tid  = threadIdx.x;
    const int wid  = tid >> 5;
    const int lane = tid & 31;

    int* STOK = (int*)(smem + SMEM_MAIN);
    {
        int rp = mtile * 128 + tid;
        STOK[tid] = g_tok[e * TOKS + (rp < cnt ? rp : cnt - 1)];
    }
    __syncthreads();

    const uint32_t sb = smem_u32(smem);
    const fp16* wghb = g_wgh + ((size_t)e * INTD + (size_t)ntile * 64) * HID;
    const fp16* wuhb = g_wuh + ((size_t)e * INTD + (size_t)ntile * 64) * HID;

    // cp.async addressing: thread -> row r0+16i, 16B chunk ch
    const int r0 = tid >> 3;
    const int ch = tid & 7;
    const uint32_t d0 = (uint32_t)(r0 * 128 + ((ch ^ (r0 & 7)) << 4));
    const char* xbase = (const char*)g_xsh;
    uint32_t offA[8];
#pragma unroll
    for (int i = 0; i < 8; i++)
        offA[i] = (uint32_t)STOK[r0 + 16 * i] * (HID * 2) + ch * 16;
    const fp16* srcG = wghb + (size_t)r0 * HID + ch * 8;
    const fp16* srcU = wuhb + (size_t)r0 * HID + ch * 8;

    const uint32_t mloc = (lane & 7) | (((lane >> 3) & 1) << 3);
    const uint32_t csel = lane >> 4;
    const uint32_t wm = (wid & 1) * 64;
    const uint32_t wn = (wid >> 1) * 32;
    uint32_t aoff[4];
#pragma unroll
    for (int mt = 0; mt < 4; mt++) {
        uint32_t r = wm + mt * 16 + mloc;
        aoff[mt] = r * 128 + ((csel ^ (r & 7)) << 4);
    }
    uint32_t goff[2];
#pragma unroll
    for (int i = 0; i < 2; i++) {
        uint32_t r = wn + i * 16 + mloc;
        goff[i] = r * 128 + ((csel ^ (r & 7)) << 4);
    }

    float cg[4][4][4] = {};
    float cu[4][4][4] = {};

    auto load_stage = [&](int stage, int k0) {
        const uint32_t stA = sb + stage * STAGE_BYTES + d0;
        const uint32_t stB = stA + 16384;
#pragma unroll
        for (int i = 0; i < 8; i++) CPA(stA + i * 2048, xbase + offA[i] + k0 * 2);
#pragma unroll
        for (int i = 0; i < 4; i++) CPA(stB + i * 2048, srcG + i * 16 * HID + k0);
#pragma unroll
        for (int i = 0; i < 4; i++) CPA(stB + 8192 + i * 2048, srcU + i * 16 * HID + k0);
    };

    load_stage(0, 0); CPC();
    load_stage(1, 64); CPC();

    const int NC = HID / 64;
    int stage = 0;
    for (int kc = 0; kc < NC; kc++) {
        CPW(1);
        __syncthreads();
        if (kc + 2 < NC) {
            int ns = stage + 2; if (ns >= 3) ns -= 3;
            load_stage(ns, (kc + 2) * 64);
        }
        CPC();

        const uint32_t sA = sb + stage * STAGE_BYTES;
        const uint32_t sB = sA + 16384;
#pragma unroll
        for (int ks = 0; ks < 4; ks++) {
            const uint32_t x = ks << 5;
            uint32_t ah[4][4], gf[8], uf[8];
#pragma unroll
            for (int mt = 0; mt < 4; mt++) LDM4(ah[mt], sA + (aoff[mt] ^ x));
            LDM4(gf,     sB + (goff[0] ^ x));
            LDM4(gf + 4, sB + (goff[1] ^ x));
            LDM4(uf,     sB + 8192 + (goff[0] ^ x));
            LDM4(uf + 4, sB + 8192 + (goff[1] ^ x));
#pragma unroll
            for (int mt = 0; mt < 4; mt++)
#pragma unroll
                for (int nt = 0; nt < 4; nt++) {
                    int b = (nt >> 1) * 4 + (nt & 1);
                    MMA(cg[mt][nt], ah[mt], gf[b], gf[b + 2]);
                    MMA(cu[mt][nt], ah[mt], uf[b], uf[b + 2]);
                }
        }
        if (++stage >= 3) stage = 0;
    }

    // epilogue: SiLU(g)*u -> fp16 act scratch
#pragma unroll
    for (int mt = 0; mt < 4; mt++) {
        int p0 = mtile * 128 + wm + mt * 16 + (lane >> 2);
        int p1 = p0 + 8;
#pragma unroll
        for (int nt = 0; nt < 4; nt++) {
            int col = ntile * 64 + wn + nt * 8 + (lane & 3) * 2;
            float a0, a1, a2, a3, gv, uv;
            gv = cg[mt][nt][0]; uv = cu[mt][nt][0]; a0 = gv / (1.f + expf(-gv)) * uv;
            gv = cg[mt][nt][1]; uv = cu[mt][nt][1]; a1 = gv / (1.f + expf(-gv)) * uv;
            gv = cg[mt][nt][2]; uv = cu[mt][nt][2]; a2 = gv / (1.f + expf(-gv)) * uv;
            gv = cg[mt][nt][3]; uv = cu[mt][nt][3]; a3 = gv / (1.f + expf(-gv)) * uv;
            if (p0 < cnt) {
                size_t idx = ((size_t)e * TOKS + p0) * INTD + col;
                __half2 hp;
                hp.x = __float2half_rn(a0); hp.y = __float2half_rn(a1);
                *(__half2*)(g_acth + idx) = hp;
            }
            if (p1 < cnt) {
                size_t idx = ((size_t)e * TOKS + p1) * INTD + col;
                __half2 hp;
                hp.x = __float2half_rn(a2); hp.y = __float2half_rn(a3);
                *(__half2*)(g_acth + idx) = hp;
            }
        }
    }
}

// ================= kernel: down GEMM + weighted scatter-add ===================
// CTA tile: M=128 slot rows x N=128 hid cols; 4 warps 2x2; warp tile 64x64
__global__ void __launch_bounds__(128, 2)
k3_down(float* __restrict__ out) {
    extern __shared__ char smem[];
    const int e     = blockIdx.x >> 5;
    const int mtile = blockIdx.x & 31;
    const int ntile = blockIdx.y;
    const int cnt   = g_counts[e];
    if (mtile * 128 >= cnt) return;

    const int tid  = threadIdx.x;
    const int wid  = tid >> 5;
    const int lane = tid & 31;

    const uint32_t sb = smem_u32(smem);
    const fp16* wdb = g_wdh + ((size_t)e * HID + (size_t)ntile * 128) * INTD;

    const int r0 = tid >> 3;
    const int ch = tid & 7;
    const uint32_t d0 = (uint32_t)(r0 * 128 + ((ch ^ (r0 & 7)) << 4));
    const char* abase = (const char*)g_acth;
    uint32_t offA[8];
#pragma unroll
    for (int i = 0; i < 8; i++) {
        int rp = mtile * 128 + r0 + 16 * i;
        if (rp >= cnt) rp = cnt - 1;
        offA[i] = (uint32_t)((e * TOKS + rp) * (INTD * 2)) + ch * 16;
    }
    const fp16* srcB = wdb + (size_t)r0 * INTD + ch * 8;

    const uint32_t mloc = (lane & 7) | (((lane >> 3) & 1) << 3);
    const uint32_t csel = lane >> 4;
    const uint32_t wm = (wid & 1) * 64;
    const uint32_t wn = (wid >> 1) * 64;
    uint32_t aoff[4];
#pragma unroll
    for (int mt = 0; mt < 4; mt++) {
        uint32_t r = wm + mt * 16 + mloc;
        aoff[mt] = r * 128 + ((csel ^ (r & 7)) << 4);
    }
    uint32_t boff[4];
#pragma unroll
    for (int i = 0; i < 4; i++) {
        uint32_t r = wn + i * 16 + mloc;
        boff[i] = r * 128 + ((csel ^ (r & 7)) << 4);
    }

    float cd[4][8][4] = {};

    auto load_stage = [&](int stage, int k0) {
        const uint32_t stA = sb + stage * STAGE_BYTES + d0;
        const uint32_t stB = stA + 16384;
#pragma unroll
        for (int i = 0; i < 8; i++) CPA(stA + i * 2048, abase + offA[i] + k0 * 2);
#pragma unroll
        for (int i = 0; i < 8; i++) CPA(stB + i * 2048, srcB + i * 16 * INTD + k0);
    };

    load_stage(0, 0); CPC();
    load_stage(1, 64); CPC();

    const int NC = INTD / 64;
    int stage = 0;
    for (int kc = 0; kc < NC; kc++) {
        CPW(1);
        __syncthreads();
        if (kc + 2 < NC) {
            int ns = stage + 2; if (ns >= 3) ns -= 3;
            load_stage(ns, (kc + 2) * 64);
        }
        CPC();

        const uint32_t sA = sb + stage * STAGE_BYTES;
        const uint32_t sB = sA + 16384;
#pragma unroll
        for (int ks = 0; ks < 4; ks++) {
            const uint32_t x = ks << 5;
            uint32_t ah[4][4], bh[16];
#pragma unroll
            for (int mt = 0; mt < 4; mt++) LDM4(ah[mt], sA + (aoff[mt] ^ x));
#pragma unroll
            for (int j = 0; j < 4; j++) LDM4(bh + j * 4, sB + (boff[j] ^ x));
#pragma unroll
            for (int mt = 0; mt < 4; mt++)
#pragma unroll
                for (int nt = 0; nt < 8; nt++) {
                    int b = (nt >> 1) * 4 + (nt & 1);
                    MMA(cd[mt][nt], ah[mt], bh[b], bh[b + 2]);
                }
        }
        if (++stage >= 3) stage = 0;
    }

    // epilogue: scale by routing weight, atomicAdd into out
#pragma unroll
    for (int mt = 0; mt < 4; mt++) {
        int p0 = mtile * 128 + wm + mt * 16 + (lane >> 2);
        int p1 = p0 + 8;
        bool v0 = p0 < cnt, v1 = p1 < cnt;
        float w0 = 0.f, w1 = 0.f;
        float *o0 = out, *o1 = out;
        if (v0) {
            w0 = g_wt[e * TOKS + p0];
            o0 = out + (size_t)g_tok[e * TOKS + p0] * HID + ntile * 128;
        }
        if (v1) {
            w1 = g_wt[e * TOKS + p1];
            o1 = out + (size_t)g_tok[e * TOKS + p1] * HID + ntile * 128;
        }
#pragma unroll
        for (int nt = 0; nt < 8; nt++) {
            int col = wn + nt * 8 + (lane & 3) * 2;
            if (v0) {
                atomicAdd(o0 + col,     w0 * cd[mt][nt][0]);
                atomicAdd(o0 + col + 1, w0 * cd[mt][nt][1]);
            }
            if (v1) {
                atomicAdd(o1 + col,     w1 * cd[mt][nt][2]);
                atomicAdd(o1 + col + 1, w1 * cd[mt][nt][3]);
            }
        }
    }
}

// ================= launch =====================================================
extern "C" void kernel_launch(void* const* d_in, const int* in_sizes, int n_in,
                              void* d_out, int out_size) {
    const float* x  = (const float*)d_in[0];
    const float* gw = (const float*)d_in[1];
    const float* wg = (const float*)d_in[2];
    const float* wu = (const float*)d_in[3];
    const float* wd = (const float*)d_in[4];
    float* out = (float*)d_out;

    const int SMEM = SMEM_MAIN + 512;
    cudaFuncSetAttribute(k2_gateup, cudaFuncAttributeMaxDynamicSharedMemorySize, SMEM);
    cudaFuncSetAttribute(k3_down,   cudaFuncAttributeMaxDynamicSharedMemorySize, SMEM);

    const int NCVT = (R_X + 3 * R_W) / 2;

    k_zero   <<<(TOKS * HID / 4 + 255) / 256, 256>>>((float4*)out, TOKS * HID / 4);
    k_router <<<TOKS / 8, 256>>>(x, gw);
    k_cvt_all<<<(NCVT + 255) / 256, 256>>>((const float4*)x, (const float4*)wg,
                                           (const float4*)wu, (const float4*)wd);
    k2_gateup<<<dim3(NE * 32, INTD / 64), 128, SMEM>>>();
    k3_down  <<<dim3(NE * 32, HID / 128), 128, SMEM>>>(out);
}

// round 11
// speedup vs baseline: 1.0630x; 1.0630x over previous
#include <cuda_runtime.h>
#include <cuda_fp16.h>
#include <cstdint>

#define TOKS 4096
#define HID  2048
#define INTD 1024
#define NE   8

typedef __half fp16;

// ---------------- persistent device scratch ----------------------------------
__device__ int   g_counts[NE];
__device__ int   g_tok [NE * TOKS];
__device__ float g_wt  [NE * TOKS];
__device__ fp16  g_xsh [TOKS * HID];
__device__ fp16  g_wgh [NE * INTD * HID];
__device__ fp16  g_wuh [NE * INTD * HID];
__device__ fp16  g_wdh [NE * HID * INTD];
__device__ fp16  g_acth[(size_t)NE * TOKS * INTD];

// ---------------- asm helpers -------------------------------------------------
__device__ __forceinline__ uint32_t smem_u32(const void* p) {
    return (uint32_t)__cvta_generic_to_shared(p);
}

#define CPA(s, g)  asm volatile("cp.async.cg.shared.global [%0], [%1], 16;" :: "r"(s), "l"(g))
#define CPC()      asm volatile("cp.async.commit_group;" ::: "memory")
#define CPW(n)     asm volatile("cp.async.wait_group %0;" :: "n"(n) : "memory")

#define LDM4(r, addr)                                                           \
    asm volatile("ldmatrix.sync.aligned.m8n8.x4.shared.b16 {%0,%1,%2,%3}, [%4];" \
        : "=r"((r)[0]), "=r"((r)[1]), "=r"((r)[2]), "=r"((r)[3]) : "r"(addr))

#define MMA(c, a, b0, b1)                                                       \
    asm volatile("mma.sync.aligned.m16n8k16.row.col.f32.f16.f16.f32 "            \
        "{%0,%1,%2,%3},{%4,%5,%6,%7},{%8,%9},{%0,%1,%2,%3};"                     \
        : "+f"((c)[0]), "+f"((c)[1]), "+f"((c)[2]), "+f"((c)[3])                 \
        : "r"((a)[0]), "r"((a)[1]), "r"((a)[2]), "r"((a)[3]), "r"(b0), "r"(b1))

// ================= kernel: zero out + counts ==================================
__global__ void __launch_bounds__(256) k_zero(float4* __restrict__ out, int n4) {
    int i = blockIdx.x * 256 + threadIdx.x;
    if (i < n4) out[i] = make_float4(0.f, 0.f, 0.f, 0.f);
    if (blockIdx.x == 0 && threadIdx.x < NE) g_counts[threadIdx.x] = 0;
}

// ================= kernel: fused fp32 -> fp16 conversion ======================
#define R_X  (TOKS * HID / 4)
#define R_W  (NE * INTD * HID / 4)
__global__ void __launch_bounds__(256)
k_cvt_all(const float4* __restrict__ x,  const float4* __restrict__ wg,
          const float4* __restrict__ wu, const float4* __restrict__ wd) {
    int base = (blockIdx.x * 256 + threadIdx.x) * 2;
    const float4* src;
    __half2* dst;
    int local;
    if (base < R_X)                { src = x;  dst = (__half2*)g_xsh; local = base; }
    else if (base < R_X + R_W)     { src = wg; dst = (__half2*)g_wgh; local = base - R_X; }
    else if (base < R_X + 2 * R_W) { src = wu; dst = (__half2*)g_wuh; local = base - R_X - R_W; }
    else                           { src = wd; dst = (__half2*)g_wdh; local = base - R_X - 2 * R_W; }
#pragma unroll
    for (int j = 0; j < 2; j++) {
        float4 v = src[local + j];
        __half2 hp0, hp1;
        hp0.x = __float2half_rn(v.x); hp0.y = __float2half_rn(v.y);
        hp1.x = __float2half_rn(v.z); hp1.y = __float2half_rn(v.w);
        dst[(local + j) * 2]     = hp0;
        dst[(local + j) * 2 + 1] = hp1;
    }
}

// ================= kernel: router (warp per token) ============================
__global__ void __launch_bounds__(256) k_router(const float* __restrict__ x,
                                                const float* __restrict__ gw) {
    int t    = blockIdx.x * 8 + (threadIdx.x >> 5);
    int lane = threadIdx.x & 31;
    if (t >= TOKS) return;
    const float* h = x + (size_t)t * HID;

    float acc[NE];
#pragma unroll
    for (int e = 0; e < NE; e++) acc[e] = 0.0f;
    for (int i = lane; i < HID; i += 32) {
        float hv = h[i];
#pragma unroll
        for (int e = 0; e < NE; e++) acc[e] += hv * gw[e * HID + i];
    }
#pragma unroll
    for (int e = 0; e < NE; e++)
#pragma unroll
        for (int o = 16; o; o >>= 1) acc[e] += __shfl_xor_sync(0xFFFFFFFFu, acc[e], o);

    if (lane == 0) {
        float mx = acc[0];
#pragma unroll
        for (int e = 1; e < NE; e++) mx = fmaxf(mx, acc[e]);
        float p[NE], s = 0.0f;
#pragma unroll
        for (int e = 0; e < NE; e++) { p[e] = expf(acc[e] - mx); s += p[e]; }
#pragma unroll
        for (int e = 0; e < NE; e++) p[e] /= s;

        int i1 = 0;
#pragma unroll
        for (int e = 1; e < NE; e++) if (p[e] > p[i1]) i1 = e;
        int i2 = (i1 == 0) ? 1 : 0;
#pragma unroll
        for (int e = 0; e < NE; e++) if (e != i1 && p[e] > p[i2]) i2 = e;

        float denom = p[i1] + p[i2];
        int pos = atomicAdd(&g_counts[i1], 1);
        g_tok[i1 * TOKS + pos] = t;
        g_wt [i1 * TOKS + pos] = p[i1] / denom;
        pos = atomicAdd(&g_counts[i2], 1);
        g_tok[i2 * TOKS + pos] = t;
        g_wt [i2 * TOKS + pos] = p[i2] / denom;
    }
}

// ================= GEMM common: M=64 CTA tiles, BK=64, 3-stage 24KB ===========
// stage layout: [A 8K: 64 rows x 128B][B 16K: 128 rows x 128B]
// swizzle: 16B chunk' = chunk ^ (row & 7)
#define STAGE_BYTES 24576
#define NSTAGE 3
#define SMEM_MAIN (NSTAGE * STAGE_BYTES)

// ================= kernel: gate+up GEMM + SiLU ================================
// CTA tile: M=64 tokens x N=64 inter (gate rows 0-63 + up rows 64-127 in B)
__global__ void __launch_bounds__(256, 3)
k2_gateup() {
    extern __shared__ char smem[];
    const int e     = blockIdx.x >> 6;
    const int mtile = blockIdx.x & 63;
    const int ntile = blockIdx.y;
    const int cnt   = g_counts[e];
    if (mtile * 64 >= cnt) return;

    const int tid  = threadIdx.x;
    const int wid  = tid >> 5;
    const int lane = tid & 31;

    int* STOK = (int*)(smem + SMEM_MAIN);
    if (tid < 64) {
        int rp = mtile * 64 + tid;
        STOK[tid] = g_tok[e * TOKS + (rp < cnt ? rp : cnt - 1)];
    }
    __syncthreads();

    const uint32_t sb = smem_u32(smem);
    const fp16* wghb = g_wgh + ((size_t)e * INTD + (size_t)ntile * 64) * HID;
    const fp16* wuhb = g_wuh + ((size_t)e * INTD + (size_t)ntile * 64) * HID;

    const int arow = tid >> 3;
    const int ach  = tid & 7;
    const uint32_t d0 = sb + (uint32_t)(arow * 128 + ((ach ^ (arow & 7)) << 4));
    const fp16* srcA0 = g_xsh + (size_t)STOK[arow]      * HID + ach * 8;
    const fp16* srcA1 = g_xsh + (size_t)STOK[arow + 32] * HID + ach * 8;
    const fp16* srcG  = wghb + (size_t)arow * HID + ach * 8;
    const fp16* srcU  = wuhb + (size_t)arow * HID + ach * 8;

    const uint32_t mloc = (lane & 7) | (((lane >> 3) & 1) << 3);
    const uint32_t csel = lane >> 4;
    const uint32_t wm = (wid & 1) * 32;
    const uint32_t wn = (wid >> 1) * 16;
    uint32_t aoff[2];
#pragma unroll
    for (int mt = 0; mt < 2; mt++) {
        uint32_t r = wm + mt * 16 + mloc;
        aoff[mt] = r * 128 + ((csel ^ (r & 7)) << 4);
    }
    const uint32_t brow = wn + mloc;
    const uint32_t boff = brow * 128 + ((csel ^ (brow & 7)) << 4);

    float cg[2][2][4] = {};
    float cu[2][2][4] = {};

    auto load_stage = [&](int stage, int k0) {
        const uint32_t st = d0 + stage * STAGE_BYTES;
        CPA(st,                 srcA0 + k0);
        CPA(st + 1 * 4096,      srcA1 + k0);
        CPA(st + 2 * 4096,      srcG  + k0);
        CPA(st + 3 * 4096,      srcG  + 32 * HID + k0);
        CPA(st + 4 * 4096,      srcU  + k0);
        CPA(st + 5 * 4096,      srcU  + 32 * HID + k0);
    };

    load_stage(0, 0); CPC();
    load_stage(1, 64); CPC();

    const int NC = HID / 64;
    int stage = 0;
    for (int kc = 0; kc < NC; kc++) {
        CPW(1);
        __syncthreads();
        if (kc + 2 < NC) {
            int ns = stage + 2; if (ns >= 3) ns -= 3;
            load_stage(ns, (kc + 2) * 64);
        }
        CPC();

        const uint32_t sA = sb + stage * STAGE_BYTES;
        const uint32_t sB = sA + 8192;

        // fragment double-buffer: prefetch ks+1 LDSM before MMAs of ks
        uint32_t ah[2][2][4], gh[2][4], uh[2][4];
        LDM4(ah[0][0], sA + aoff[0]);
        LDM4(ah[0][1], sA + aoff[1]);
        LDM4(gh[0], sB + boff);
        LDM4(uh[0], sB + 8192 + boff);
#pragma unroll
        for (int ks = 0; ks < 4; ks++) {
            const int cur = ks & 1, nxt = cur ^ 1;
            if (ks < 3) {
                const uint32_t x = (uint32_t)(ks + 1) << 5;
                LDM4(ah[nxt][0], sA + (aoff[0] ^ x));
                LDM4(ah[nxt][1], sA + (aoff[1] ^ x));
                LDM4(gh[nxt], sB + (boff ^ x));
                LDM4(uh[nxt], sB + 8192 + (boff ^ x));
            }
#pragma unroll
            for (int mt = 0; mt < 2; mt++)
#pragma unroll
                for (int nt = 0; nt < 2; nt++) {
                    MMA(cg[mt][nt], ah[cur][mt], gh[cur][nt], gh[cur][nt + 2]);
                    MMA(cu[mt][nt], ah[cur][mt], uh[cur][nt], uh[cur][nt + 2]);
                }
        }
        if (++stage >= 3) stage = 0;
    }

    // epilogue: SiLU(g)*u -> fp16 act scratch
#pragma unroll
    for (int mt = 0; mt < 2; mt++) {
        int p0 = mtile * 64 + wm + mt * 16 + (lane >> 2);
        int p1 = p0 + 8;
#pragma unroll
        for (int nt = 0; nt < 2; nt++) {
            int col = ntile * 64 + wn + nt * 8 + (lane & 3) * 2;
            float a0, a1, a2, a3, gv, uv;
            gv = cg[mt][nt][0]; uv = cu[mt][nt][0]; a0 = gv / (1.f + expf(-gv)) * uv;
            gv = cg[mt][nt][1]; uv = cu[mt][nt][1]; a1 = gv / (1.f + expf(-gv)) * uv;
            gv = cg[mt][nt][2]; uv = cu[mt][nt][2]; a2 = gv / (1.f + expf(-gv)) * uv;
            gv = cg[mt][nt][3]; uv = cu[mt][nt][3]; a3 = gv / (1.f + expf(-gv)) * uv;
            if (p0 < cnt) {
                size_t idx = ((size_t)e * TOKS + p0) * INTD + col;
                __half2 hp;
                hp.x = __float2half_rn(a0); hp.y = __float2half_rn(a1);
                *(__half2*)(g_acth + idx) = hp;
            }
            if (p1 < cnt) {
                size_t idx = ((size_t)e * TOKS + p1) * INTD + col;
                __half2 hp;
                hp.x = __float2half_rn(a2); hp.y = __float2half_rn(a3);
                *(__half2*)(g_acth + idx) = hp;
            }
        }
    }
}

// ================= kernel: down GEMM + weighted scatter-add ===================
// CTA tile: M=64 slot rows x N=128 hid cols, K=INTD
__global__ void __launch_bounds__(256, 3)
k3_down(float* __restrict__ out) {
    extern __shared__ char smem[];
    const int e     = blockIdx.x >> 6;
    const int mtile = blockIdx.x & 63;
    const int ntile = blockIdx.y;
    const int cnt   = g_counts[e];
    if (mtile * 64 >= cnt) return;

    const int tid  = threadIdx.x;
    const int wid  = tid >> 5;
    const int lane = tid & 31;

    const uint32_t sb = smem_u32(smem);
    const fp16* ath = g_acth + (size_t)e * TOKS * INTD;
    const fp16* wdb = g_wdh + ((size_t)e * HID + (size_t)ntile * 128) * INTD;

    const int arow = tid >> 3;
    const int ach  = tid & 7;
    const uint32_t d0 = sb + (uint32_t)(arow * 128 + ((ach ^ (arow & 7)) << 4));
    int rp0 = mtile * 64 + arow;
    int rp1 = rp0 + 32;
    const fp16* srcA0 = ath + (size_t)(rp0 < cnt ? rp0 : cnt - 1) * INTD + ach * 8;
    const fp16* srcA1 = ath + (size_t)(rp1 < cnt ? rp1 : cnt - 1) * INTD + ach * 8;
    const fp16* srcB  = wdb + (size_t)arow * INTD + ach * 8;

    const uint32_t mloc = (lane & 7) | (((lane >> 3) & 1) << 3);
    const uint32_t csel = lane >> 4;
    const uint32_t wm = (wid & 1) * 32;
    const uint32_t wn = (wid >> 1) * 32;
    uint32_t aoff[2];
#pragma unroll
    for (int mt = 0; mt < 2; mt++) {
        uint32_t r = wm + mt * 16 + mloc;
        aoff[mt] = r * 128 + ((csel ^ (r & 7)) << 4);
    }
    uint32_t boff[2];
#pragma unroll
    for (int i = 0; i < 2; i++) {
        uint32_t r = wn + i * 16 + mloc;
        boff[i] = r * 128 + ((csel ^ (r & 7)) << 4);
    }

    float cd[2][4][4] = {};

    auto load_stage = [&](int stage, int k0) {
        const uint32_t st = d0 + stage * STAGE_BYTES;
        CPA(st,            srcA0 + k0);
        CPA(st + 1 * 4096, srcA1 + k0);
        CPA(st + 2 * 4096, srcB  + k0);
        CPA(st + 3 * 4096, srcB  + 32 * INTD + k0);
        CPA(st + 4 * 4096, srcB  + 64 * INTD + k0);
        CPA(st + 5 * 4096, srcB  + 96 * INTD + k0);
    };

    load_stage(0, 0); CPC();
    load_stage(1, 64); CPC();

    const int NC = INTD / 64;
    int stage = 0;
    for (int kc = 0; kc < NC; kc++) {
        CPW(1);
        __syncthreads();
        if (kc + 2 < NC) {
            int ns = stage + 2; if (ns >= 3) ns -= 3;
            load_stage(ns, (kc + 2) * 64);
        }
        CPC();

        const uint32_t sA = sb + stage * STAGE_BYTES;
        const uint32_t sB = sA + 8192;

        // fragment double-buffer
        uint32_t ah[2][2][4], dh[2][8];
        LDM4(ah[0][0], sA + aoff[0]);
        LDM4(ah[0][1], sA + aoff[1]);
        LDM4(dh[0],     sB + boff[0]);
        LDM4(dh[0] + 4, sB + boff[1]);
#pragma unroll
        for (int ks = 0; ks < 4; ks++) {
            const int cur = ks & 1, nxt = cur ^ 1;
            if (ks < 3) {
                const uint32_t x = (uint32_t)(ks + 1) << 5;
                LDM4(ah[nxt][0], sA + (aoff[0] ^ x));
                LDM4(ah[nxt][1], sA + (aoff[1] ^ x));
                LDM4(dh[nxt],     sB + (boff[0] ^ x));
                LDM4(dh[nxt] + 4, sB + (boff[1] ^ x));
            }
#pragma unroll
            for (int mt = 0; mt < 2; mt++)
#pragma unroll
                for (int nt = 0; nt < 4; nt++) {
                    int b0 = (nt >> 1) * 4 + (nt & 1);
                    MMA(cd[mt][nt], ah[cur][mt], dh[cur][b0], dh[cur][b0 + 2]);
                }
        }
        if (++stage >= 3) stage = 0;
    }

    // epilogue: scale by routing weight, atomicAdd into out
#pragma unroll
    for (int mt = 0; mt < 2; mt++) {
        int p0 = mtile * 64 + wm + mt * 16 + (lane >> 2);
        int p1 = p0 + 8;
        bool v0 = p0 < cnt, v1 = p1 < cnt;
        float w0 = 0.f, w1 = 0.f;
        float *o0 = out, *o1 = out;
        if (v0) {
            w0 = g_wt[e * TOKS + p0];
            o0 = out + (size_t)g_tok[e * TOKS + p0] * HID + ntile * 128;
        }
        if (v1) {
            w1 = g_wt[e * TOKS + p1];
            o1 = out + (size_t)g_tok[e * TOKS + p1] * HID + ntile * 128;
        }
#pragma unroll
        for (int nt = 0; nt < 4; nt++) {
            int col = wn + nt * 8 + (lane & 3) * 2;
            if (v0) {
                atomicAdd(o0 + col,     w0 * cd[mt][nt][0]);
                atomicAdd(o0 + col + 1, w0 * cd[mt][nt][1]);
            }
            if (v1) {
                atomicAdd(o1 + col,     w1 * cd[mt][nt][2]);
                atomicAdd(o1 + col + 1, w1 * cd[mt][nt][3]);
            }
        }
    }
}

// ================= launch =====================================================
extern "C" void kernel_launch(void* const* d_in, const int* in_sizes, int n_in,
                              void* d_out, int out_size) {
    const float* x  = (const float*)d_in[0];
    const float* gw = (const float*)d_in[1];
    const float* wg = (const float*)d_in[2];
    const float* wu = (const float*)d_in[3];
    const float* wd = (const float*)d_in[4];
    float* out = (float*)d_out;

    const int SMEM = SMEM_MAIN + 512;
    cudaFuncSetAttribute(k2_gateup, cudaFuncAttributeMaxDynamicSharedMemorySize, SMEM);
    cudaFuncSetAttribute(k3_down,   cudaFuncAttributeMaxDynamicSharedMemorySize, SMEM);

    const int NCVT = (R_X + 3 * R_W) / 2;

    k_zero   <<<(TOKS * HID / 4 + 255) / 256, 256>>>((float4*)out, TOKS * HID / 4);
    k_router <<<TOKS / 8, 256>>>(x, gw);
    k_cvt_all<<<(NCVT + 255) / 256, 256>>>((const float4*)x, (const float4*)wg,
                                           (const float4*)wu, (const float4*)wd);
    k2_gateup<<<dim3(NE * 64, INTD / 64), 256, SMEM>>>();
    k3_down  <<<dim3(NE * 64, HID / 128), 256, SMEM>>>(out);
}